// round 16
// baseline (speedup 1.0000x reference)
#include <cuda_runtime.h>
#include <cuda_fp16.h>
#include <mma.h>
#include <math.h>
#include <stdint.h>

using namespace nvcuda;

#define WINN 4
#define LTOK 36

// Dynamic conv weights, fp16 hi/lo, layout [w*9+p][ic(64)][oc stride 72]
#define WROW 72
__device__ __half g_Whi[36 * 64 * WROW];
__device__ __half g_Wlo[36 * 64 * WROW];

__device__ __forceinline__ uint32_t smem_u32(const void* p) {
    uint32_t a;
    asm("{ .reg .u64 t; cvta.to.shared.u64 t, %1; cvt.u32.u64 %0, t; }" : "=r"(a) : "l"(p));
    return a;
}
__device__ __forceinline__ void cp16(uint32_t dst, const void* src) {
    asm volatile("cp.async.cg.shared.global [%0], [%1], 16;\n"
                 :: "r"(dst), "l"(src) : "memory");
}
#define CP_COMMIT() asm volatile("cp.async.commit_group;\n" ::: "memory")
#define CP_WAIT0()  asm volatile("cp.async.wait_group 0;\n" ::: "memory")

// ===========================================================================
// Stage 1: build dynamic conv kernels (one block per oc b = blockIdx.x).
// ===========================================================================
#define SQ_STRIDE 193
#define SA_STRIDE 65
#define SK_STRIDE 65

__global__ __launch_bounds__(288) void stage1_kernel(
    const float* __restrict__ conv_w, const float* __restrict__ w_qkv,
    const float* __restrict__ b_qkv,  const float* __restrict__ w_out,
    const float* __restrict__ b_out,  const float* __restrict__ se_w1,
    const float* __restrict__ se_b1,  const float* __restrict__ se_w2,
    const float* __restrict__ se_b2)
{
    const int b   = blockIdx.x;
    const int tid = threadIdx.x;

    __shared__ float sA[LTOK * SA_STRIDE];
    __shared__ float sQ[LTOK * SQ_STRIDE];
    __shared__ float pooled[4][64];
    __shared__ float hr[4][4];

    for (int t = tid; t < LTOK * 64; t += 288) {
        int l = t >> 6, i = t & 63;
        int w = l / 9, p = l - w * 9;
        sA[l * SA_STRIDE + i] = conv_w[(((w * 64 + b) * 64 + i) * 9) + p];
    }
    __syncthreads();

    {
        const int l  = tid % 36;
        const int j0 = tid / 36;
        const float* kr = sA + l * SA_STRIDE;
        for (int k = 0; k < 24; k++) {
            int j = j0 + 8 * k;
            float acc = b_qkv[j];
            const float* wr = w_qkv + j * 64;
            #pragma unroll
            for (int i = 0; i < 64; i++) acc = fmaf(kr[i], wr[i], acc);
            sQ[l * SQ_STRIDE + j] = acc;
        }
    }
    __syncthreads();

    {
        int h = tid / 36, l = tid - h * 36;
        const int qo = h * 8;
        const float scale = 0.35355339059327373f;
        float qv[8];
        #pragma unroll
        for (int d = 0; d < 8; d++) qv[d] = sQ[l * SQ_STRIDE + qo + d] * scale;

        float sc[36];
        float mx = -1e30f;
        for (int m = 0; m < 36; m++) {
            float s = 0.f;
            #pragma unroll
            for (int d = 0; d < 8; d++)
                s = fmaf(qv[d], sQ[m * SQ_STRIDE + 64 + qo + d], s);
            sc[m] = s;
            mx = fmaxf(mx, s);
        }
        float sum = 0.f;
        for (int m = 0; m < 36; m++) { float e = expf(sc[m] - mx); sc[m] = e; sum += e; }
        float inv = 1.f / sum;
        float o[8];
        #pragma unroll
        for (int d = 0; d < 8; d++) o[d] = 0.f;
        for (int m = 0; m < 36; m++) {
            float a = sc[m];
            #pragma unroll
            for (int d = 0; d < 8; d++)
                o[d] = fmaf(a, sQ[m * SQ_STRIDE + 128 + qo + d], o[d]);
        }
        #pragma unroll
        for (int d = 0; d < 8; d++) sA[l * SA_STRIDE + qo + d] = o[d] * inv;
    }
    __syncthreads();

    {
        const int l  = tid % 36;
        const int j0 = tid / 36;
        const float* orow = sA + l * SA_STRIDE;
        for (int k = 0; k < 8; k++) {
            int j = j0 + 8 * k;
            float acc = b_out[j];
            const float* wr = w_out + j * 64;
            #pragma unroll
            for (int i = 0; i < 64; i++) acc = fmaf(orow[i], wr[i], acc);
            sQ[l * SK_STRIDE + j] = acc;
        }
    }
    __syncthreads();

    if (tid < 256) {
        int w = tid >> 6, i = tid & 63;
        float s = 0.f;
        #pragma unroll
        for (int p = 0; p < 9; p++) s += sQ[(w * 9 + p) * SK_STRIDE + i];
        pooled[w][i] = s * (1.f / 9.f);
    }
    __syncthreads();
    if (tid < 16) {
        int w = tid >> 2, r = tid & 3;
        float acc = se_b1[w * 4 + r];
        #pragma unroll
        for (int i = 0; i < 64; i++)
            acc = fmaf(pooled[w][i], se_w1[(w * 4 + r) * 64 + i], acc);
        hr[w][r] = fmaxf(acc, 0.f);
    }
    __syncthreads();
    if (tid < 256) {
        int w = tid >> 6, i = tid & 63;   // i = ic
        float acc = se_b2[w * 64 + i];
        #pragma unroll
        for (int r = 0; r < 4; r++)
            acc = fmaf(hr[w][r], se_w2[(w * 64 + i) * 4 + r], acc);
        float g = 1.f / (1.f + expf(-acc));
        #pragma unroll
        for (int p = 0; p < 9; p++) {
            float v = sQ[(w * 9 + p) * SK_STRIDE + i] * g;
            __half hi = __float2half(v);
            __half lo = __float2half(v - __half2float(hi));
            int idx = ((w * 9 + p) * 64 + i) * WROW + b;
            g_Whi[idx] = hi;
            g_Wlo[idx] = lo;
        }
    }
}

// ===========================================================================
// Stage 2: fp16 2-pass WMMA implicit-GEMM conv + LN + residual, taps-outer.
// CTA = 16x16 px tile, 256 threads, 2 CTAs/SM.
// A: full 64-ic halo converted in-CTA (hoisted index math, half2 stores),
//    layout [pos(324)][72].
// W: per-tap [64 ic][72 oc] hi+lo, double-buffered cp.async.
// ===========================================================================
#define AROW   72
#define A_ELEMS (324 * AROW)                     // 23328 fp16
#define W_TAP   (64 * WROW)                      // 4608 per hi/lo
#define WBUF_E  (2 * W_TAP)
#define SMEM2_BYTES ((A_ELEMS + 2 * WBUF_E) * 2) // 83520 B
#define DSTRIDE 68

typedef wmma::fragment<wmma::matrix_a, 16, 16, 16, __half, wmma::row_major> FragA;
typedef wmma::fragment<wmma::matrix_b, 16, 16, 16, __half, wmma::row_major> FragB;
typedef wmma::fragment<wmma::accumulator, 16, 16, 16, float> FragC;

__global__ __launch_bounds__(256, 2) void stage2_kernel(
    const float* __restrict__ x, const float* __restrict__ ln_w,
    const float* __restrict__ ln_b, float* __restrict__ out)
{
    extern __shared__ __half sb[];
    __half* Ash = sb;                            // [324][72]

    const int blk  = blockIdx.x;
    const int tile = blk & 63;
    const int w    = (blk >> 6) & 3;
    const int b    = blk >> 8;
    const int ty0  = (tile >> 3) << 4;
    const int tx0  = (tile & 7) << 4;
    const int wh   = w >> 1, ww = w & 1;

    const int tid = threadIdx.x;
    const int wid = tid >> 5;

    FragC acc[2][4];
    #pragma unroll
    for (int r = 0; r < 2; r++)
        #pragma unroll
        for (int n = 0; n < 4; n++) wmma::fill_fragment(acc[r][n], 0.f);

    // W tap staging into buffer bp (async)
    auto stageW = [&](int p, int bp) {
        const size_t base = (size_t)(w * 9 + p) * W_TAP;
        __half* Wb = sb + A_ELEMS + bp * WBUF_E;
        for (int t = tid; t < 1152; t += 256) {
            int hl  = t >= 576;
            int e8  = (hl ? t - 576 : t) * 8;
            cp16(smem_u32(Wb + hl * W_TAP + e8),
                 (hl ? g_Wlo : g_Whi) + base + e8);
        }
    };

    // ---- prologue: W(0) async + A halo convert (hoisted index, half2) ----
    stageW(0, 0);
    CP_COMMIT();
    {
        const float* xb = x + (size_t)b * (64 * 65536);
        int off0 = 0, off1 = 0;
        bool v0, v1 = false;
        {
            int pos = tid;
            int hrow = pos / 18, hcol = pos - hrow * 18;
            int ly = ty0 + hrow - 1, lx = tx0 + hcol - 1;
            v0 = (ly >= 0 && ly < 128 && lx >= 0 && lx < 128);
            off0 = (wh * 128 + (v0 ? ly : 0)) * 256 + ww * 128 + (v0 ? lx : 0);
        }
        if (tid < 68) {
            int pos = tid + 256;
            int hrow = pos / 18, hcol = pos - hrow * 18;
            int ly = ty0 + hrow - 1, lx = tx0 + hcol - 1;
            v1 = (ly >= 0 && ly < 128 && lx >= 0 && lx < 128);
            off1 = (wh * 128 + (v1 ? ly : 0)) * 256 + ww * 128 + (v1 ? lx : 0);
        }
        __half* d0 = Ash + tid * AROW;
        __half* d1 = Ash + (tid + 256) * AROW;
        #pragma unroll 4
        for (int ic = 0; ic < 64; ic += 2) {
            const float* p0 = xb + (size_t)ic * 65536;
            const float* p1 = xb + (size_t)(ic + 1) * 65536;
            float a0 = v0 ? p0[off0] : 0.f;
            float b0 = v0 ? p1[off0] : 0.f;
            *(__half2*)(d0 + ic) = __floats2half2_rn(a0, b0);
            if (tid < 68) {
                float a1 = v1 ? p0[off1] : 0.f;
                float b1 = v1 ? p1[off1] : 0.f;
                *(__half2*)(d1 + ic) = __floats2half2_rn(a1, b1);
            }
        }
    }
    CP_WAIT0();
    __syncthreads();

    // ---- mainloop: 9 taps outer, 4 ic k-steps inner ----
    #pragma unroll 1
    for (int p = 0; p < 9; p++) {
        if (p < 8) { stageW(p + 1, (p + 1) & 1); CP_COMMIT(); }

        const int dy = p / 3, dx = p - 3 * dy;
        const __half* Whi = sb + A_ELEMS + (p & 1) * WBUF_E;
        const __half* Wlo = Whi + W_TAP;

        #pragma unroll
        for (int kc = 0; kc < 4; kc++) {
            FragB bh[4], bl[4];
            FragA af[2];
            const __half* wbh = Whi + (kc * 16) * WROW;
            const __half* wbl = Wlo + (kc * 16) * WROW;
            #pragma unroll
            for (int n = 0; n < 4; n++) {
                wmma::load_matrix_sync(bh[n], wbh + n * 16, WROW);
                wmma::load_matrix_sync(bl[n], wbl + n * 16, WROW);
            }
            #pragma unroll
            for (int r = 0; r < 2; r++) {
                const int aoff = ((wid * 2 + r + dy) * 18 + dx) * AROW + kc * 16;
                wmma::load_matrix_sync(af[r], Ash + aoff, AROW);
            }
            #pragma unroll
            for (int r = 0; r < 2; r++)
                #pragma unroll
                for (int n = 0; n < 4; n++)
                    wmma::mma_sync(acc[r][n], af[r], bh[n], acc[r][n]);
            #pragma unroll
            for (int r = 0; r < 2; r++)
                #pragma unroll
                for (int n = 0; n < 4; n++)
                    wmma::mma_sync(acc[r][n], af[r], bl[n], acc[r][n]);
        }
        if (p < 8) CP_WAIT0();
        __syncthreads();
    }

    // ---- epilogue: dump to smem, LN over oc, residual, store ----
    float* D = (float*)sb;                           // [256 px][68]
    #pragma unroll
    for (int r = 0; r < 2; r++) {
        const int yrow = wid * 2 + r;
        #pragma unroll
        for (int n = 0; n < 4; n++)
            wmma::store_matrix_sync(D + (yrow * 16) * DSTRIDE + n * 16,
                                    acc[r][n], DSTRIDE, wmma::mem_row_major);
    }
    __syncthreads();

    {
        const int lane = tid & 31;
        const int y  = tid >> 4, xq = tid & 15;
        const float* drow = D + tid * DSTRIDE;
        // LN sums with per-lane rotated oc order -> conflict-free banks
        float s = 0.f, sq = 0.f;
        #pragma unroll
        for (int t = 0; t < 64; t++) {
            float d = drow[(t + lane) & 63];
            s += d;
            sq = fmaf(d, d, sq);
        }
        float mu   = s * (1.f / 64.f);
        float rstd = rsqrtf(sq * (1.f / 64.f) - mu * mu + 1e-5f);
        const int gy = wh * 128 + ty0 + y;
        const int gx = ww * 128 + tx0 + xq;
        #pragma unroll 4
        for (int oc = 0; oc < 64; oc++) {
            size_t gi = ((size_t)(b * 64 + oc) * 256 + gy) * 256 + gx;
            out[gi] = x[gi] + (drow[oc] - mu) * rstd * ln_w[oc] + ln_b[oc];
        }
    }
}

// ===========================================================================
extern "C" void kernel_launch(void* const* d_in, const int* in_sizes, int n_in,
                              void* d_out, int out_size)
{
    (void)in_sizes; (void)n_in; (void)out_size;
    const float* x      = (const float*)d_in[0];
    const float* conv_w = (const float*)d_in[1];
    const float* w_qkv  = (const float*)d_in[2];
    const float* b_qkv  = (const float*)d_in[3];
    const float* w_out  = (const float*)d_in[4];
    const float* b_out  = (const float*)d_in[5];
    const float* se_w1  = (const float*)d_in[6];
    const float* se_b1  = (const float*)d_in[7];
    const float* se_w2  = (const float*)d_in[8];
    const float* se_b2  = (const float*)d_in[9];
    const float* ln_w   = (const float*)d_in[10];
    const float* ln_b   = (const float*)d_in[11];
    float* out = (float*)d_out;

    cudaFuncSetAttribute(stage2_kernel,
                         cudaFuncAttributeMaxDynamicSharedMemorySize, SMEM2_BYTES);

    stage1_kernel<<<64, 288>>>(conv_w, w_qkv, b_qkv, w_out, b_out,
                               se_w1, se_b1, se_w2, se_b2);
    stage2_kernel<<<2048, 256, SMEM2_BYTES>>>(x, ln_w, ln_b, out);
}

// round 17
// speedup vs baseline: 1.3440x; 1.3440x over previous
#include <cuda_runtime.h>
#include <cuda_fp16.h>
#include <mma.h>
#include <math.h>
#include <stdint.h>

using namespace nvcuda;

#define WINN 4
#define LTOK 36

// Dynamic conv weights, fp16 hi/lo, layout [w*9+p][ic(64)][oc stride 72]
#define WROW 72
__device__ __half g_Whi[36 * 64 * WROW];
__device__ __half g_Wlo[36 * 64 * WROW];

__device__ __forceinline__ uint32_t smem_u32(const void* p) {
    uint32_t a;
    asm("{ .reg .u64 t; cvta.to.shared.u64 t, %1; cvt.u32.u64 %0, t; }" : "=r"(a) : "l"(p));
    return a;
}
__device__ __forceinline__ void cp16(uint32_t dst, const void* src) {
    asm volatile("cp.async.cg.shared.global [%0], [%1], 16;\n"
                 :: "r"(dst), "l"(src) : "memory");
}
#define CP_COMMIT() asm volatile("cp.async.commit_group;\n" ::: "memory")
#define CP_WAIT0()  asm volatile("cp.async.wait_group 0;\n" ::: "memory")

// ===========================================================================
// Stage 1: build dynamic conv kernels (one block per oc b = blockIdx.x).
// ===========================================================================
#define SQ_STRIDE 193
#define SA_STRIDE 65
#define SK_STRIDE 65

__global__ __launch_bounds__(288) void stage1_kernel(
    const float* __restrict__ conv_w, const float* __restrict__ w_qkv,
    const float* __restrict__ b_qkv,  const float* __restrict__ w_out,
    const float* __restrict__ b_out,  const float* __restrict__ se_w1,
    const float* __restrict__ se_b1,  const float* __restrict__ se_w2,
    const float* __restrict__ se_b2)
{
    const int b   = blockIdx.x;
    const int tid = threadIdx.x;

    __shared__ float sA[LTOK * SA_STRIDE];
    __shared__ float sQ[LTOK * SQ_STRIDE];
    __shared__ float pooled[4][64];
    __shared__ float hr[4][4];

    for (int t = tid; t < LTOK * 64; t += 288) {
        int l = t >> 6, i = t & 63;
        int w = l / 9, p = l - w * 9;
        sA[l * SA_STRIDE + i] = conv_w[(((w * 64 + b) * 64 + i) * 9) + p];
    }
    __syncthreads();

    {
        const int l  = tid % 36;
        const int j0 = tid / 36;
        const float* kr = sA + l * SA_STRIDE;
        for (int k = 0; k < 24; k++) {
            int j = j0 + 8 * k;
            float acc = b_qkv[j];
            const float* wr = w_qkv + j * 64;
            #pragma unroll
            for (int i = 0; i < 64; i++) acc = fmaf(kr[i], wr[i], acc);
            sQ[l * SQ_STRIDE + j] = acc;
        }
    }
    __syncthreads();

    {
        int h = tid / 36, l = tid - h * 36;
        const int qo = h * 8;
        const float scale = 0.35355339059327373f;
        float qv[8];
        #pragma unroll
        for (int d = 0; d < 8; d++) qv[d] = sQ[l * SQ_STRIDE + qo + d] * scale;

        float sc[36];
        float mx = -1e30f;
        for (int m = 0; m < 36; m++) {
            float s = 0.f;
            #pragma unroll
            for (int d = 0; d < 8; d++)
                s = fmaf(qv[d], sQ[m * SQ_STRIDE + 64 + qo + d], s);
            sc[m] = s;
            mx = fmaxf(mx, s);
        }
        float sum = 0.f;
        for (int m = 0; m < 36; m++) { float e = expf(sc[m] - mx); sc[m] = e; sum += e; }
        float inv = 1.f / sum;
        float o[8];
        #pragma unroll
        for (int d = 0; d < 8; d++) o[d] = 0.f;
        for (int m = 0; m < 36; m++) {
            float a = sc[m];
            #pragma unroll
            for (int d = 0; d < 8; d++)
                o[d] = fmaf(a, sQ[m * SQ_STRIDE + 128 + qo + d], o[d]);
        }
        #pragma unroll
        for (int d = 0; d < 8; d++) sA[l * SA_STRIDE + qo + d] = o[d] * inv;
    }
    __syncthreads();

    {
        const int l  = tid % 36;
        const int j0 = tid / 36;
        const float* orow = sA + l * SA_STRIDE;
        for (int k = 0; k < 8; k++) {
            int j = j0 + 8 * k;
            float acc = b_out[j];
            const float* wr = w_out + j * 64;
            #pragma unroll
            for (int i = 0; i < 64; i++) acc = fmaf(orow[i], wr[i], acc);
            sQ[l * SK_STRIDE + j] = acc;
        }
    }
    __syncthreads();

    if (tid < 256) {
        int w = tid >> 6, i = tid & 63;
        float s = 0.f;
        #pragma unroll
        for (int p = 0; p < 9; p++) s += sQ[(w * 9 + p) * SK_STRIDE + i];
        pooled[w][i] = s * (1.f / 9.f);
    }
    __syncthreads();
    if (tid < 16) {
        int w = tid >> 2, r = tid & 3;
        float acc = se_b1[w * 4 + r];
        #pragma unroll
        for (int i = 0; i < 64; i++)
            acc = fmaf(pooled[w][i], se_w1[(w * 4 + r) * 64 + i], acc);
        hr[w][r] = fmaxf(acc, 0.f);
    }
    __syncthreads();
    if (tid < 256) {
        int w = tid >> 6, i = tid & 63;   // i = ic
        float acc = se_b2[w * 64 + i];
        #pragma unroll
        for (int r = 0; r < 4; r++)
            acc = fmaf(hr[w][r], se_w2[(w * 64 + i) * 4 + r], acc);
        float g = 1.f / (1.f + expf(-acc));
        #pragma unroll
        for (int p = 0; p < 9; p++) {
            float v = sQ[(w * 9 + p) * SK_STRIDE + i] * g;
            __half hi = __float2half(v);
            __half lo = __float2half(v - __half2float(hi));
            int idx = ((w * 9 + p) * 64 + i) * WROW + b;
            g_Whi[idx] = hi;
            g_Wlo[idx] = lo;
        }
    }
}

// ===========================================================================
// Stage 2: fp16 2-pass WMMA implicit-GEMM conv + LN + residual, taps-outer.
// CTA = 16x16 px tile, 256 threads, 2 CTAs/SM.
// Warp tile: 4 image rows x 32 oc (rg = wid&3, ng = wid>>2) — cuts per-kc
// LDSM count 80 -> 64 vs the 2-row x 64-oc mapping.
// A: full 64-ic halo converted in-CTA (R14 pos-major loop), [pos(324)][72].
// W: per-tap [64 ic][72 oc] hi+lo, double-buffered cp.async.
// ===========================================================================
#define AROW   72
#define A_ELEMS (324 * AROW)                     // 23328 fp16
#define W_TAP   (64 * WROW)                      // 4608 per hi/lo
#define WBUF_E  (2 * W_TAP)
#define SMEM2_BYTES ((A_ELEMS + 2 * WBUF_E) * 2) // 83520 B
#define DSTRIDE 68

typedef wmma::fragment<wmma::matrix_a, 16, 16, 16, __half, wmma::row_major> FragA;
typedef wmma::fragment<wmma::matrix_b, 16, 16, 16, __half, wmma::row_major> FragB;
typedef wmma::fragment<wmma::accumulator, 16, 16, 16, float> FragC;

__global__ __launch_bounds__(256, 2) void stage2_kernel(
    const float* __restrict__ x, const float* __restrict__ ln_w,
    const float* __restrict__ ln_b, float* __restrict__ out)
{
    extern __shared__ __half sb[];
    __half* Ash = sb;                            // [324][72]

    const int blk  = blockIdx.x;
    const int tile = blk & 63;
    const int w    = (blk >> 6) & 3;
    const int b    = blk >> 8;
    const int ty0  = (tile >> 3) << 4;
    const int tx0  = (tile & 7) << 4;
    const int wh   = w >> 1, ww = w & 1;

    const int tid = threadIdx.x;
    const int wid = tid >> 5;
    const int rg  = wid & 3;        // row group: image rows rg*4 .. rg*4+3
    const int ng  = wid >> 2;       // n group: oc frags ng*2, ng*2+1

    FragC acc[4][2];
    #pragma unroll
    for (int r = 0; r < 4; r++)
        #pragma unroll
        for (int j = 0; j < 2; j++) wmma::fill_fragment(acc[r][j], 0.f);

    // W tap staging into buffer bp (async)
    auto stageW = [&](int p, int bp) {
        const size_t base = (size_t)(w * 9 + p) * W_TAP;
        __half* Wb = sb + A_ELEMS + bp * WBUF_E;
        for (int t = tid; t < 1152; t += 256) {
            int hl  = t >= 576;
            int e8  = (hl ? t - 576 : t) * 8;
            cp16(smem_u32(Wb + hl * W_TAP + e8),
                 (hl ? g_Wlo : g_Whi) + base + e8);
        }
    };

    // ---- prologue: W(0) async + full A halo convert (fp32 -> fp16) ----
    stageW(0, 0);
    CP_COMMIT();
    {
        const float* xb = x + (size_t)b * (64 * 65536);
        // pos-major so consecutive lanes hit consecutive x addresses
        for (int i = tid; i < 324 * 64; i += 256) {
            int ic  = i / 324;
            int pos = i - ic * 324;
            int hrow = pos / 18, hcol = pos - hrow * 18;
            int ly = ty0 + hrow - 1, lx = tx0 + hcol - 1;
            float v = 0.f;
            if (ly >= 0 && ly < 128 && lx >= 0 && lx < 128)
                v = xb[(size_t)ic * 65536 + (wh * 128 + ly) * 256 + ww * 128 + lx];
            Ash[pos * AROW + ic] = __float2half(v);
        }
    }
    CP_WAIT0();
    __syncthreads();

    // ---- mainloop: 9 taps outer, 4 ic k-steps inner ----
    #pragma unroll 1
    for (int p = 0; p < 9; p++) {
        if (p < 8) { stageW(p + 1, (p + 1) & 1); CP_COMMIT(); }

        const int dy = p / 3, dx = p - 3 * dy;
        const __half* Whi = sb + A_ELEMS + (p & 1) * WBUF_E;
        const __half* Wlo = Whi + W_TAP;

        #pragma unroll
        for (int kc = 0; kc < 4; kc++) {
            FragB bh[2], bl[2];
            FragA af[4];
            const __half* wbh = Whi + (kc * 16) * WROW + ng * 32;
            const __half* wbl = Wlo + (kc * 16) * WROW + ng * 32;
            #pragma unroll
            for (int j = 0; j < 2; j++) {
                wmma::load_matrix_sync(bh[j], wbh + j * 16, WROW);
                wmma::load_matrix_sync(bl[j], wbl + j * 16, WROW);
            }
            #pragma unroll
            for (int r = 0; r < 4; r++) {
                const int aoff = ((rg * 4 + r + dy) * 18 + dx) * AROW + kc * 16;
                wmma::load_matrix_sync(af[r], Ash + aoff, AROW);
            }
            // pass-outer: each acc reused 8 mmas apart
            #pragma unroll
            for (int r = 0; r < 4; r++)
                #pragma unroll
                for (int j = 0; j < 2; j++)
                    wmma::mma_sync(acc[r][j], af[r], bh[j], acc[r][j]);
            #pragma unroll
            for (int r = 0; r < 4; r++)
                #pragma unroll
                for (int j = 0; j < 2; j++)
                    wmma::mma_sync(acc[r][j], af[r], bl[j], acc[r][j]);
        }
        if (p < 8) CP_WAIT0();
        __syncthreads();
    }

    // ---- epilogue: dump to smem, LN over oc, residual, store ----
    float* D = (float*)sb;                           // [256 px][68]
    #pragma unroll
    for (int r = 0; r < 4; r++) {
        const int yrow = rg * 4 + r;
        #pragma unroll
        for (int j = 0; j < 2; j++)
            wmma::store_matrix_sync(D + (yrow * 16) * DSTRIDE + (ng * 2 + j) * 16,
                                    acc[r][j], DSTRIDE, wmma::mem_row_major);
    }
    __syncthreads();

    {
        const int y  = tid >> 4, xq = tid & 15;
        const float* drow = D + tid * DSTRIDE;
        float s = 0.f, sq = 0.f;
        #pragma unroll
        for (int oc = 0; oc < 64; oc++) {
            float d = drow[oc];
            s += d;
            sq = fmaf(d, d, sq);
        }
        float mu   = s * (1.f / 64.f);
        float rstd = rsqrtf(sq * (1.f / 64.f) - mu * mu + 1e-5f);
        const int gy = wh * 128 + ty0 + y;
        const int gx = ww * 128 + tx0 + xq;
        #pragma unroll 4
        for (int oc = 0; oc < 64; oc++) {
            size_t gi = ((size_t)(b * 64 + oc) * 256 + gy) * 256 + gx;
            out[gi] = x[gi] + (drow[oc] - mu) * rstd * ln_w[oc] + ln_b[oc];
        }
    }
}

// ===========================================================================
extern "C" void kernel_launch(void* const* d_in, const int* in_sizes, int n_in,
                              void* d_out, int out_size)
{
    (void)in_sizes; (void)n_in; (void)out_size;
    const float* x      = (const float*)d_in[0];
    const float* conv_w = (const float*)d_in[1];
    const float* w_qkv  = (const float*)d_in[2];
    const float* b_qkv  = (const float*)d_in[3];
    const float* w_out  = (const float*)d_in[4];
    const float* b_out  = (const float*)d_in[5];
    const float* se_w1  = (const float*)d_in[6];
    const float* se_b1  = (const float*)d_in[7];
    const float* se_w2  = (const float*)d_in[8];
    const float* se_b2  = (const float*)d_in[9];
    const float* ln_w   = (const float*)d_in[10];
    const float* ln_b   = (const float*)d_in[11];
    float* out = (float*)d_out;

    cudaFuncSetAttribute(stage2_kernel,
                         cudaFuncAttributeMaxDynamicSharedMemorySize, SMEM2_BYTES);

    stage1_kernel<<<64, 288>>>(conv_w, w_qkv, b_qkv, w_out, b_out,
                               se_w1, se_b1, se_w2, se_b2);
    stage2_kernel<<<2048, 256, SMEM2_BYTES>>>(x, ln_w, ln_b, out);
}